// round 7
// baseline (speedup 1.0000x reference)
#include <cuda_runtime.h>
#include <math.h>
#include <stdint.h>

#define HIDDEN 1024
#define MEM 32
#define KEY 32
#define VAL 32
#define BATCH 2048
#define TLEN 64
#define BT (BATCH*TLEN)   /* 131072 */
#define NWARMUP 4

/* ---------------- proj tiling --------------------------------------------- */
#define BMp 128            /* rows per CTA */
#define BNp 96             /* proj cols (gate handled separately) */
#define BKp 16             /* k per chunk */
#define NCHUNKS (HIDDEN/BKp)   /* 64 */
/* 256 threads: colgrp = tid&15 (6 cols each), rowgrp = tid>>4 (8 rows each) */

/* ---------------- scratch (static device arrays; no allocation) ----------- */
__device__ float  g_Q [BT*KEY];
__device__ float  g_FK[BT*KEY];
__device__ float  g_FV[BT*VAL];
__device__ float  g_G [BT];
/* B weights, duplicated float2, interleaved: [chunk][kk][j*16+colgrp] */
__device__ float2 g_Bdup[NCHUNKS][BKp][BNp];

/* ---------------- helpers -------------------------------------------------- */
__device__ __forceinline__ void ffma2(unsigned long long& d,
                                      unsigned long long a,
                                      unsigned long long b) {
    asm("fma.rn.f32x2 %0, %1, %2, %0;" : "+l"(d) : "l"(a), "l"(b));
}
__device__ __forceinline__ float f2lo(unsigned long long v) {
    return __uint_as_float((unsigned)(v & 0xffffffffu));
}
__device__ __forceinline__ float f2hi(unsigned long long v) {
    return __uint_as_float((unsigned)(v >> 32));
}
__device__ __forceinline__ unsigned redux_umax(unsigned v) {
    unsigned r;
    asm("redux.sync.max.u32 %0, %1, 0xffffffff;" : "=r"(r) : "r"(v));
    return r;
}
__device__ __forceinline__ unsigned redux_umin(unsigned v) {
    unsigned r;
    asm("redux.sync.min.u32 %0, %1, 0xffffffff;" : "=r"(r) : "r"(v));
    return r;
}

/* ---------------- prep: duplicate + interleave weights --------------------- */
__global__ __launch_bounds__(256) void prep_kernel(
    const float* __restrict__ Wq, const float* __restrict__ Wk,
    const float* __restrict__ Wv)
{
    int idx = blockIdx.x * 256 + threadIdx.x;    /* 64*16*96 = 98304 */
    int c   = idx / (BKp * BNp);
    int rem = idx % (BKp * BNp);
    int kk  = rem / BNp;
    int col = rem % BNp;
    int k   = c * BKp + kk;

    float b;
    if      (col < 32) b = Wq[col * HIDDEN + k];
    else if (col < 64) b = Wk[(col - 32) * HIDDEN + k];
    else               b = Wv[(col - 64) * HIDDEN + k];

    int colgrp = col / 6;
    int j      = col % 6;
    g_Bdup[c][kk][j * 16 + colgrp] = make_float2(b, b);
}

/* ---------------- proj kernel: FFMA2 (f32x2) GEMM, 256 threads ------------- */
__global__ __launch_bounds__(256) void proj_kernel(
    const float* __restrict__ hmat,
    const float* __restrict__ Wg, const float* __restrict__ bg,
    const float* __restrict__ bq, const float* __restrict__ bk_,
    const float* __restrict__ bv)
{
    __shared__ float  As[2][BKp][BMp + 2];   /* k-major, stride 130 (even) */
    __shared__ float2 Bs[2][BKp][BNp];       /* duplicated pairs, interleaved */
    __shared__ float  Gs[2][BKp];

    const int tid    = threadIdx.x;
    const int colgrp = tid & 15;
    const int rowgrp = tid >> 4;            /* 0..15, 8 rows each */
    const long r0    = (long)blockIdx.x * BMp;

    unsigned long long acc[4][6];
    #pragma unroll
    for (int i = 0; i < 4; i++)
        #pragma unroll
        for (int j = 0; j < 6; j++) acc[i][j] = 0ull;
    float accg = 0.f;

    /* prologue: load chunk 0 into regs */
    float4 av[2];        /* A: 2048 floats / 256 thr = 2 float4 */
    float4 bvv[3];       /* Bdup: 1536 float2 = 768 float4 / 256 thr = 3 */
    float  gv;
    {
        #pragma unroll
        for (int q = 0; q < 2; q++) {
            int i   = tid + 256 * q;      /* 0..511 */
            int row = i >> 2;
            int kg  = (i & 3) * 4;
            av[q] = *(const float4*)(hmat + (r0 + row) * HIDDEN + kg);
        }
        const float4* bsrc = (const float4*)&g_Bdup[0][0][0];
        #pragma unroll
        for (int q = 0; q < 3; q++) bvv[q] = bsrc[tid + 256 * q];
        gv = (tid < BKp) ? Wg[tid] : 0.f;
    }
    /* STS chunk 0 -> stage 0 */
    {
        #pragma unroll
        for (int q = 0; q < 2; q++) {
            int i   = tid + 256 * q;
            int row = i >> 2;
            int kg  = (i & 3) * 4;
            As[0][kg+0][row] = av[q].x;
            As[0][kg+1][row] = av[q].y;
            As[0][kg+2][row] = av[q].z;
            As[0][kg+3][row] = av[q].w;
        }
        float4* bdst = (float4*)&Bs[0][0][0];
        #pragma unroll
        for (int q = 0; q < 3; q++) bdst[tid + 256 * q] = bvv[q];
        if (tid < BKp) Gs[0][tid] = gv;
    }
    __syncthreads();

    for (int c = 0; c < NCHUNKS; c++) {
        const int s = c & 1;

        /* prefetch chunk c+1 into regs */
        if (c + 1 < NCHUNKS) {
            const int k0n = (c + 1) * BKp;
            #pragma unroll
            for (int q = 0; q < 2; q++) {
                int i   = tid + 256 * q;
                int row = i >> 2;
                int kg  = (i & 3) * 4;
                av[q] = *(const float4*)(hmat + (r0 + row) * HIDDEN + k0n + kg);
            }
            const float4* bsrc = (const float4*)&g_Bdup[c + 1][0][0];
            #pragma unroll
            for (int q = 0; q < 3; q++) bvv[q] = bsrc[tid + 256 * q];
            gv = (tid < BKp) ? Wg[k0n + tid] : 0.f;
        }

        /* compute 16 kk from stage s */
        #pragma unroll
        for (int kk = 0; kk < BKp; kk++) {
            unsigned long long a[4], b[6];
            #pragma unroll
            for (int i = 0; i < 4; i++)
                a[i] = *(const unsigned long long*)&As[s][kk][rowgrp * 8 + 2 * i];
            #pragma unroll
            for (int j = 0; j < 6; j++)
                b[j] = *(const unsigned long long*)&Bs[s][kk][j * 16 + colgrp];
            #pragma unroll
            for (int i = 0; i < 4; i++)
                #pragma unroll
                for (int j = 0; j < 6; j++)
                    ffma2(acc[i][j], a[i], b[j]);
            if (tid < 128) accg = fmaf(As[s][kk][tid], Gs[s][kk], accg);
        }

        /* store prefetched chunk to other stage */
        if (c + 1 < NCHUNKS) {
            const int sn = s ^ 1;
            #pragma unroll
            for (int q = 0; q < 2; q++) {
                int i   = tid + 256 * q;
                int row = i >> 2;
                int kg  = (i & 3) * 4;
                As[sn][kg+0][row] = av[q].x;
                As[sn][kg+1][row] = av[q].y;
                As[sn][kg+2][row] = av[q].z;
                As[sn][kg+3][row] = av[q].w;
            }
            float4* bdst = (float4*)&Bs[sn][0][0];
            #pragma unroll
            for (int q = 0; q < 3; q++) bdst[tid + 256 * q] = bvv[q];
            if (tid < BKp) Gs[sn][tid] = gv;
        }
        __syncthreads();
    }

    /* epilogue */
    const int C = colgrp * 6;
    float bias[6];
    #pragma unroll
    for (int j = 0; j < 6; j++) {
        int col = C + j;
        bias[j] = (col < 32) ? bq[col] : (col < 64) ? bk_[col - 32] : bv[col - 64];
    }
    #pragma unroll
    for (int i = 0; i < 4; i++) {
        long row0 = r0 + rowgrp * 8 + 2 * i;
        float v0[6], v1[6];
        #pragma unroll
        for (int j = 0; j < 6; j++) {
            v0[j] = f2lo(acc[i][j]) + bias[j];
            v1[j] = f2hi(acc[i][j]) + bias[j];
        }
        #pragma unroll
        for (int jj = 0; jj < 6; jj += 2) {
            int col = C + jj;
            float* dst;
            int cc;
            if      (col < 32) { dst = g_Q;  cc = col; }
            else if (col < 64) { dst = g_FK; cc = col - 32; }
            else               { dst = g_FV; cc = col - 64; }
            *(float2*)(dst + row0 * 32 + cc)       = make_float2(v0[jj], v0[jj+1]);
            *(float2*)(dst + (row0 + 1) * 32 + cc) = make_float2(v1[jj], v1[jj+1]);
        }
    }
    if (tid < 128) g_G[r0 + tid] = accg + bg[0];
}

/* ---------------- Kernel 2: recurrence, one warp per batch ----------------- */
#define NW 2

__global__ __launch_bounds__(32*NW) void rnn_kernel(float* __restrict__ es,
                                                    float* __restrict__ ps)
{
    __shared__ float Vs [NW][MEM][VAL+1];
    __shared__ float qs [NW][KEY];
    __shared__ float fks[NW][KEY];
    __shared__ float fvs[NW][VAL];
    __shared__ float ats[NW][MEM];

    const int w    = threadIdx.x >> 5;
    const int lane = threadIdx.x & 31;
    const int b    = blockIdx.x * NW + w;
    const unsigned FULL = 0xffffffffu;
    const float scale = 0.17677669529663688f;

    float K[KEY];
    #pragma unroll
    for (int j = 0; j < KEY; j++) { K[j] = 0.f; Vs[w][lane][j] = 0.f; }
    float Tf = 0.f, msk = 0.f;
    __syncwarp();

    const long row0 = (long)b * TLEN;
    float qv  = g_Q [row0*KEY + lane];
    float fkv = g_FK[row0*KEY + lane];
    float fvv = g_FV[row0*VAL + lane];
    float gx  = g_G [row0];

    for (int t = 0; t < TLEN; t++) {
        const long row  = row0 + t;
        const long nrow = (t < TLEN-1) ? row + 1 : row;

        float nq  = g_Q [nrow*KEY + lane];
        float nfk = g_FK[nrow*KEY + lane];
        float nfv = g_FV[nrow*VAL + lane];
        float ngx = g_G [nrow];

        qs [w][lane] = qv;
        fks[w][lane] = fkv;
        fvs[w][lane] = fvv;
        __syncwarp();

        float lg = 0.f;
        #pragma unroll
        for (int j = 0; j < KEY; j++) lg = fmaf(K[j], qs[w][j], lg);
        lg *= scale;
        float lm = fmaf(1.0f - msk, -1e9f, lg);

        unsigned ub  = __float_as_uint(lm);
        unsigned key = ub ^ ((unsigned)((int)ub >> 31) | 0x80000000u);
        unsigned km  = redux_umax(key);
        unsigned mb  = (km & 0x80000000u) ? (km ^ 0x80000000u) : ~km;
        float mx = __uint_as_float(mb);

        float ex = expf(lm - mx);
        float sm = ex;
        #pragma unroll
        for (int off = 16; off; off >>= 1)
            sm += __shfl_xor_sync(FULL, sm, off);
        float attn = ex / sm;
        ats[w][lane] = attn;

        unsigned ab = __float_as_uint(attn);
        unsigned am = redux_umax(ab);
        int amax = __ffs(__ballot_sync(FULL, ab == am)) - 1;
        __syncwarp();

        float r = 0.f;
        #pragma unroll
        for (int m = 0; m < MEM; m++)
            r = fmaf(ats[w][m], Vs[w][m][lane], r);

        unsigned bal = __ballot_sync(FULL, msk != 0.f);
        bool empty = (bal == 0u);
        bool warm  = (t < NWARMUP);
        float p = 1.f / (1.f + expf(-gx));
        float gate = (empty || warm) ? 0.f : p;
        bool wr = empty || warm || (gx < 0.f);

        float om = 1.0f - gate;
        float e  = gate * r + om * fvv;
        es[row*VAL + lane] = e;
        if (lane == 0) ps[row] = p;

        float evv = Tf + msk * 0.001f;
        unsigned eb = __float_as_uint(evv);
        unsigned em = redux_umin(eb);
        int evict = __ffs(__ballot_sync(FULL, eb == em)) - 1;

        if (wr && lane == evict) {
            msk = 1.f;
            #pragma unroll
            for (int j = 0; j < KEY; j++) {
                K[j] = fks[w][j];
                Vs[w][lane][j] = fvs[w][j];
            }
        }
        int bslot = wr ? evict : amax;
        float A = Tf * 0.85f;
        Tf = (lane == bslot) ? (A + (1.0f - A)) : A;
        __syncwarp();

        qv = nq; fkv = nfk; fvv = nfv; gx = ngx;
    }
}

/* ---------------- launch ---------------------------------------------------- */
extern "C" void kernel_launch(void* const* d_in, const int* in_sizes, int n_in,
                              void* d_out, int out_size)
{
    const float* h  = (const float*)d_in[0];
    const float* Wg = (const float*)d_in[1];
    const float* bg = (const float*)d_in[2];
    const float* Wq = (const float*)d_in[3];
    const float* bq = (const float*)d_in[4];
    const float* Wk = (const float*)d_in[5];
    const float* bk = (const float*)d_in[6];
    const float* Wv = (const float*)d_in[7];
    const float* bv = (const float*)d_in[8];

    float* es = (float*)d_out;
    float* ps = es + ((long)out_size - BT);

    prep_kernel<<<(NCHUNKS*BKp*BNp)/256, 256>>>(Wq, Wk, Wv);
    proj_kernel<<<BT/BMp, 256>>>(h, Wg, bg, bq, bk, bv);
    rnn_kernel<<<BATCH/NW, 32*NW>>>(es, ps);
}

// round 8
// speedup vs baseline: 1.1440x; 1.1440x over previous
#include <cuda_runtime.h>
#include <math.h>
#include <stdint.h>

#define HIDDEN 1024
#define MEM 32
#define KEY 32
#define VAL 32
#define BATCH 2048
#define TLEN 64
#define BT (BATCH*TLEN)   /* 131072 */
#define NWARMUP 4

/* ---------------- proj tiling --------------------------------------------- */
#define BMp 128            /* rows per tile */
#define BNp 96             /* proj cols (gate handled separately) */
#define BKp 16             /* k per chunk */
#define NCHUNKS (HIDDEN/BKp)   /* 64 */
#define NTILES (BT/BMp)        /* 1024 */
#define PGRID 296              /* persistent CTAs (2 per SM target) */
/* 256 threads: colgrp = tid&15 (6 cols each), rowgrp = tid>>4 (8 rows each) */

/* ---------------- scratch (static device arrays; no allocation) ----------- */
__device__ float g_Q [BT*KEY];
__device__ float g_FK[BT*KEY];
__device__ float g_FV[BT*VAL];
__device__ float g_G [BT];
/* B weights, scalar, interleaved: [chunk][kk][j*16+colgrp] */
__device__ float g_B[NCHUNKS][BKp][BNp];
__device__ unsigned g_tile_ctr;

/* ---------------- helpers -------------------------------------------------- */
__device__ __forceinline__ void ffma2(unsigned long long& d,
                                      unsigned long long a,
                                      unsigned long long b) {
    asm("fma.rn.f32x2 %0, %1, %2, %0;" : "+l"(d) : "l"(a), "l"(b));
}
__device__ __forceinline__ unsigned long long dup2(float b) {
    unsigned long long r;
    unsigned u = __float_as_uint(b);
    asm("mov.b64 %0, {%1, %1};" : "=l"(r) : "r"(u));
    return r;
}
__device__ __forceinline__ float f2lo(unsigned long long v) {
    return __uint_as_float((unsigned)(v & 0xffffffffu));
}
__device__ __forceinline__ float f2hi(unsigned long long v) {
    return __uint_as_float((unsigned)(v >> 32));
}
__device__ __forceinline__ unsigned redux_umax(unsigned v) {
    unsigned r;
    asm("redux.sync.max.u32 %0, %1, 0xffffffff;" : "=r"(r) : "r"(v));
    return r;
}
__device__ __forceinline__ unsigned redux_umin(unsigned v) {
    unsigned r;
    asm("redux.sync.min.u32 %0, %1, 0xffffffff;" : "=r"(r) : "r"(v));
    return r;
}

/* ---------------- prep: interleave weights, reset tile counter ------------- */
__global__ __launch_bounds__(256) void prep_kernel(
    const float* __restrict__ Wq, const float* __restrict__ Wk,
    const float* __restrict__ Wv)
{
    if (blockIdx.x == 0 && threadIdx.x == 0) g_tile_ctr = 0u;

    int idx = blockIdx.x * 256 + threadIdx.x;    /* 64*16*96 = 98304 */
    int c   = idx / (BKp * BNp);
    int rem = idx % (BKp * BNp);
    int kk  = rem / BNp;
    int col = rem % BNp;
    int k   = c * BKp + kk;

    float b;
    if      (col < 32) b = Wq[col * HIDDEN + k];
    else if (col < 64) b = Wk[(col - 32) * HIDDEN + k];
    else               b = Wv[(col - 64) * HIDDEN + k];

    int colgrp = col / 6;
    int j      = col % 6;
    g_B[c][kk][j * 16 + colgrp] = b;
}

/* ---------------- proj kernel: persistent FFMA2 (f32x2) GEMM --------------- */
__global__ __launch_bounds__(256) void proj_kernel(
    const float* __restrict__ hmat,
    const float* __restrict__ Wg, const float* __restrict__ bg,
    const float* __restrict__ bq, const float* __restrict__ bk_,
    const float* __restrict__ bv)
{
    __shared__ float As[2][BKp][BMp + 2];   /* k-major, stride 130 (even) */
    __shared__ float Bs[2][BKp][BNp];       /* scalar, interleaved */
    __shared__ float Gs[2][BKp];
    __shared__ unsigned tile_s;

    const int tid    = threadIdx.x;
    const int colgrp = tid & 15;
    const int rowgrp = tid >> 4;            /* 0..15, 8 rows each */

    /* loop-invariant bias */
    const int C = colgrp * 6;
    float bias[6];
    #pragma unroll
    for (int j = 0; j < 6; j++) {
        int col = C + j;
        bias[j] = (col < 32) ? bq[col] : (col < 64) ? bk_[col - 32] : bv[col - 64];
    }
    const float bgv = bg[0];

    for (;;) {
        if (tid == 0) tile_s = atomicAdd(&g_tile_ctr, 1u);
        __syncthreads();
        const unsigned tile = tile_s;
        if (tile >= NTILES) break;
        const long r0 = (long)tile * BMp;

        unsigned long long acc[4][6];
        #pragma unroll
        for (int i = 0; i < 4; i++)
            #pragma unroll
            for (int j = 0; j < 6; j++) acc[i][j] = 0ull;
        float accg = 0.f;

        /* prologue: load chunk 0 into regs */
        float4 av[2];        /* A: 2048 floats / 256 thr = 2 float4 */
        float2 bvv[3];       /* B: 1536 floats / 256 thr = 3 float2 */
        float  gv;
        {
            #pragma unroll
            for (int q = 0; q < 2; q++) {
                int i   = tid + 256 * q;      /* 0..511 */
                int row = i >> 2;
                int kg  = (i & 3) * 4;
                av[q] = *(const float4*)(hmat + (r0 + row) * HIDDEN + kg);
            }
            const float2* bsrc = (const float2*)&g_B[0][0][0];
            #pragma unroll
            for (int q = 0; q < 3; q++) bvv[q] = bsrc[tid + 256 * q];
            gv = (tid < BKp) ? Wg[tid] : 0.f;
        }
        /* STS chunk 0 -> stage 0 */
        {
            #pragma unroll
            for (int q = 0; q < 2; q++) {
                int i   = tid + 256 * q;
                int row = i >> 2;
                int kg  = (i & 3) * 4;
                As[0][kg+0][row] = av[q].x;
                As[0][kg+1][row] = av[q].y;
                As[0][kg+2][row] = av[q].z;
                As[0][kg+3][row] = av[q].w;
            }
            float2* bdst = (float2*)&Bs[0][0][0];
            #pragma unroll
            for (int q = 0; q < 3; q++) bdst[tid + 256 * q] = bvv[q];
            if (tid < BKp) Gs[0][tid] = gv;
        }
        __syncthreads();

        for (int c = 0; c < NCHUNKS; c++) {
            const int s = c & 1;

            /* prefetch chunk c+1 into regs */
            if (c + 1 < NCHUNKS) {
                const int k0n = (c + 1) * BKp;
                #pragma unroll
                for (int q = 0; q < 2; q++) {
                    int i   = tid + 256 * q;
                    int row = i >> 2;
                    int kg  = (i & 3) * 4;
                    av[q] = *(const float4*)(hmat + (r0 + row) * HIDDEN + k0n + kg);
                }
                const float2* bsrc = (const float2*)&g_B[c + 1][0][0];
                #pragma unroll
                for (int q = 0; q < 3; q++) bvv[q] = bsrc[tid + 256 * q];
                gv = (tid < BKp) ? Wg[k0n + tid] : 0.f;
            }

            /* compute 16 kk from stage s */
            #pragma unroll
            for (int kk = 0; kk < BKp; kk++) {
                unsigned long long a[4], b[6];
                #pragma unroll
                for (int i = 0; i < 4; i++)
                    a[i] = *(const unsigned long long*)&As[s][kk][rowgrp * 8 + 2 * i];
                #pragma unroll
                for (int j = 0; j < 6; j++)
                    b[j] = dup2(Bs[s][kk][j * 16 + colgrp]);
                #pragma unroll
                for (int i = 0; i < 4; i++)
                    #pragma unroll
                    for (int j = 0; j < 6; j++)
                        ffma2(acc[i][j], a[i], b[j]);
                if (tid < 128) accg = fmaf(As[s][kk][tid], Gs[s][kk], accg);
            }

            /* store prefetched chunk to other stage */
            if (c + 1 < NCHUNKS) {
                const int sn = s ^ 1;
                #pragma unroll
                for (int q = 0; q < 2; q++) {
                    int i   = tid + 256 * q;
                    int row = i >> 2;
                    int kg  = (i & 3) * 4;
                    As[sn][kg+0][row] = av[q].x;
                    As[sn][kg+1][row] = av[q].y;
                    As[sn][kg+2][row] = av[q].z;
                    As[sn][kg+3][row] = av[q].w;
                }
                float2* bdst = (float2*)&Bs[sn][0][0];
                #pragma unroll
                for (int q = 0; q < 3; q++) bdst[tid + 256 * q] = bvv[q];
                if (tid < BKp) Gs[sn][tid] = gv;
            }
            __syncthreads();
        }

        /* epilogue */
        #pragma unroll
        for (int i = 0; i < 4; i++) {
            long row0 = r0 + rowgrp * 8 + 2 * i;
            float v0[6], v1[6];
            #pragma unroll
            for (int j = 0; j < 6; j++) {
                v0[j] = f2lo(acc[i][j]) + bias[j];
                v1[j] = f2hi(acc[i][j]) + bias[j];
            }
            #pragma unroll
            for (int jj = 0; jj < 6; jj += 2) {
                int col = C + jj;
                float* dst;
                int cc;
                if      (col < 32) { dst = g_Q;  cc = col; }
                else if (col < 64) { dst = g_FK; cc = col - 32; }
                else               { dst = g_FV; cc = col - 64; }
                *(float2*)(dst + row0 * 32 + cc)       = make_float2(v0[jj], v0[jj+1]);
                *(float2*)(dst + (row0 + 1) * 32 + cc) = make_float2(v1[jj], v1[jj+1]);
            }
        }
        if (tid < 128) g_G[r0 + tid] = accg + bgv;
    }
}

/* ---------------- Kernel 2: recurrence, one warp per batch ----------------- */
#define NW 2

__global__ __launch_bounds__(32*NW) void rnn_kernel(float* __restrict__ es,
                                                    float* __restrict__ ps)
{
    __shared__ float Vs [NW][MEM][VAL+1];
    __shared__ float qs [NW][KEY];
    __shared__ float fks[NW][KEY];
    __shared__ float fvs[NW][VAL];
    __shared__ float ats[NW][MEM];

    const int w    = threadIdx.x >> 5;
    const int lane = threadIdx.x & 31;
    const int b    = blockIdx.x * NW + w;
    const unsigned FULL = 0xffffffffu;
    const float scale = 0.17677669529663688f;

    float K[KEY];
    #pragma unroll
    for (int j = 0; j < KEY; j++) { K[j] = 0.f; Vs[w][lane][j] = 0.f; }
    float Tf = 0.f, msk = 0.f;
    __syncwarp();

    const long row0 = (long)b * TLEN;
    float qv  = g_Q [row0*KEY + lane];
    float fkv = g_FK[row0*KEY + lane];
    float fvv = g_FV[row0*VAL + lane];
    float gx  = g_G [row0];

    for (int t = 0; t < TLEN; t++) {
        const long row  = row0 + t;
        const long nrow = (t < TLEN-1) ? row + 1 : row;

        float nq  = g_Q [nrow*KEY + lane];
        float nfk = g_FK[nrow*KEY + lane];
        float nfv = g_FV[nrow*VAL + lane];
        float ngx = g_G [nrow];

        qs [w][lane] = qv;
        fks[w][lane] = fkv;
        fvs[w][lane] = fvv;
        __syncwarp();

        float lg = 0.f;
        #pragma unroll
        for (int j = 0; j < KEY; j++) lg = fmaf(K[j], qs[w][j], lg);
        lg *= scale;
        float lm = fmaf(1.0f - msk, -1e9f, lg);

        unsigned ub  = __float_as_uint(lm);
        unsigned key = ub ^ ((unsigned)((int)ub >> 31) | 0x80000000u);
        unsigned km  = redux_umax(key);
        unsigned mb  = (km & 0x80000000u) ? (km ^ 0x80000000u) : ~km;
        float mx = __uint_as_float(mb);

        float ex = expf(lm - mx);
        float sm = ex;
        #pragma unroll
        for (int off = 16; off; off >>= 1)
            sm += __shfl_xor_sync(FULL, sm, off);
        float attn = ex / sm;
        ats[w][lane] = attn;

        unsigned ab = __float_as_uint(attn);
        unsigned am = redux_umax(ab);
        int amax = __ffs(__ballot_sync(FULL, ab == am)) - 1;
        __syncwarp();

        float r = 0.f;
        #pragma unroll
        for (int m = 0; m < MEM; m++)
            r = fmaf(ats[w][m], Vs[w][m][lane], r);

        unsigned bal = __ballot_sync(FULL, msk != 0.f);
        bool empty = (bal == 0u);
        bool warm  = (t < NWARMUP);
        float p = 1.f / (1.f + expf(-gx));
        float gate = (empty || warm) ? 0.f : p;
        bool wr = empty || warm || (gx < 0.f);

        float om = 1.0f - gate;
        float e  = gate * r + om * fvv;
        es[row*VAL + lane] = e;
        if (lane == 0) ps[row] = p;

        float evv = Tf + msk * 0.001f;
        unsigned eb = __float_as_uint(evv);
        unsigned em = redux_umin(eb);
        int evict = __ffs(__ballot_sync(FULL, eb == em)) - 1;

        if (wr && lane == evict) {
            msk = 1.f;
            #pragma unroll
            for (int j = 0; j < KEY; j++) {
                K[j] = fks[w][j];
                Vs[w][lane][j] = fvs[w][j];
            }
        }
        int bslot = wr ? evict : amax;
        float A = Tf * 0.85f;
        Tf = (lane == bslot) ? (A + (1.0f - A)) : A;
        __syncwarp();

        qv = nq; fkv = nfk; fvv = nfv; gx = ngx;
    }
}

/* ---------------- launch ---------------------------------------------------- */
extern "C" void kernel_launch(void* const* d_in, const int* in_sizes, int n_in,
                              void* d_out, int out_size)
{
    const float* h  = (const float*)d_in[0];
    const float* Wg = (const float*)d_in[1];
    const float* bg = (const float*)d_in[2];
    const float* Wq = (const float*)d_in[3];
    const float* bq = (const float*)d_in[4];
    const float* Wk = (const float*)d_in[5];
    const float* bk = (const float*)d_in[6];
    const float* Wv = (const float*)d_in[7];
    const float* bv = (const float*)d_in[8];

    float* es = (float*)d_out;
    float* ps = es + ((long)out_size - BT);

    prep_kernel<<<(NCHUNKS*BKp*BNp)/256, 256>>>(Wq, Wk, Wv);
    proj_kernel<<<PGRID, 256>>>(h, Wg, bg, bq, bk, bv);
    rnn_kernel<<<BATCH/NW, 32*NW>>>(es, ps);
}

// round 9
// speedup vs baseline: 1.1961x; 1.0455x over previous
#include <cuda_runtime.h>
#include <math.h>
#include <stdint.h>

#define HIDDEN 1024
#define MEM 32
#define KEY 32
#define VAL 32
#define BATCH 2048
#define TLEN 64
#define BT (BATCH*TLEN)   /* 131072 */
#define NWARMUP 4

/* ---------------- proj tiling --------------------------------------------- */
#define BMp 128            /* rows per CTA */
#define BNp 96             /* proj cols (gate handled separately) */
#define BKp 16             /* k per chunk */
#define NCHUNKS (HIDDEN/BKp)   /* 64 */
/* 256 threads: colgrp = tid&15 (6 cols each), rowgrp = tid>>4 (8 rows each) */

/* ---------------- scratch (static device arrays; no allocation) ----------- */
__device__ float g_Q [BT*KEY];
__device__ float g_FK[BT*KEY];
__device__ float g_FV[BT*VAL];
__device__ float g_G [BT];
/* B weights: kk-paired, interleaved: [chunk][kkpair][j*16+colgrp][e=kk&1] */
__device__ float g_B2[NCHUNKS][BKp/2][BNp][2];

/* ---------------- helpers -------------------------------------------------- */
__device__ __forceinline__ void ffma2(unsigned long long& d,
                                      unsigned long long a,
                                      unsigned long long b) {
    asm("fma.rn.f32x2 %0, %1, %2, %0;" : "+l"(d) : "l"(a), "l"(b));
}
__device__ __forceinline__ unsigned long long dup2(float b) {
    unsigned long long r;
    unsigned u = __float_as_uint(b);
    asm("mov.b64 %0, {%1, %1};" : "=l"(r) : "r"(u));
    return r;
}
__device__ __forceinline__ float f2lo(unsigned long long v) {
    return __uint_as_float((unsigned)(v & 0xffffffffu));
}
__device__ __forceinline__ float f2hi(unsigned long long v) {
    return __uint_as_float((unsigned)(v >> 32));
}
__device__ __forceinline__ unsigned redux_umax(unsigned v) {
    unsigned r;
    asm("redux.sync.max.u32 %0, %1, 0xffffffff;" : "=r"(r) : "r"(v));
    return r;
}
__device__ __forceinline__ unsigned redux_umin(unsigned v) {
    unsigned r;
    asm("redux.sync.min.u32 %0, %1, 0xffffffff;" : "=r"(r) : "r"(v));
    return r;
}

/* ---------------- prep: pack weights (kk-paired, interleaved) -------------- */
__global__ __launch_bounds__(256) void prep_kernel(
    const float* __restrict__ Wq, const float* __restrict__ Wk,
    const float* __restrict__ Wv)
{
    int idx = blockIdx.x * 256 + threadIdx.x;    /* 64*16*96 = 98304 */
    int c   = idx / (BKp * BNp);
    int rem = idx % (BKp * BNp);
    int kk  = rem / BNp;
    int col = rem % BNp;
    int k   = c * BKp + kk;

    float b;
    if      (col < 32) b = Wq[col * HIDDEN + k];
    else if (col < 64) b = Wk[(col - 32) * HIDDEN + k];
    else               b = Wv[(col - 64) * HIDDEN + k];

    int colgrp = col / 6;
    int j      = col % 6;
    g_B2[c][kk >> 1][j * 16 + colgrp][kk & 1] = b;
}

/* ---------------- dummy kernels (shift ncu capture onto proj) -------------- */
__global__ void dummy_kernel(int x) { if (x == 12345) g_G[0] = 0.f; }

/* ---------------- proj kernel: FFMA2 (f32x2) GEMM, 256 threads ------------- */
__global__ __launch_bounds__(256) void proj_kernel(
    const float* __restrict__ hmat,
    const float* __restrict__ Wg, const float* __restrict__ bg,
    const float* __restrict__ bq, const float* __restrict__ bk_,
    const float* __restrict__ bv)
{
    __shared__ float  As[2][BKp][BMp + 4];   /* k-major, stride 132 (16B-aligned rows) */
    __shared__ float2 Bs[2][BKp/2][BNp];     /* kk-paired, interleaved */
    __shared__ float  Gs[2][BKp];

    const int tid    = threadIdx.x;
    const int colgrp = tid & 15;
    const int rowgrp = tid >> 4;            /* 0..15, 8 rows each */
    const long r0    = (long)blockIdx.x * BMp;

    unsigned long long acc[4][6];
    #pragma unroll
    for (int i = 0; i < 4; i++)
        #pragma unroll
        for (int j = 0; j < 6; j++) acc[i][j] = 0ull;
    float accg = 0.f;

    /* prologue: load chunk 0 into regs */
    float4 av[2];        /* A: 2048 floats / 256 thr = 2 float4 */
    float2 bvv[3];       /* B: 1536 floats / 256 thr = 3 float2 */
    float  gv;
    {
        #pragma unroll
        for (int q = 0; q < 2; q++) {
            int i   = tid + 256 * q;      /* 0..511 */
            int row = i >> 2;
            int kg  = (i & 3) * 4;
            av[q] = *(const float4*)(hmat + (r0 + row) * HIDDEN + kg);
        }
        const float2* bsrc = (const float2*)&g_B2[0][0][0][0];
        #pragma unroll
        for (int q = 0; q < 3; q++) bvv[q] = bsrc[tid + 256 * q];
        gv = (tid < BKp) ? Wg[tid] : 0.f;
    }
    /* STS chunk 0 -> stage 0 */
    {
        #pragma unroll
        for (int q = 0; q < 2; q++) {
            int i   = tid + 256 * q;
            int row = i >> 2;
            int kg  = (i & 3) * 4;
            As[0][kg+0][row] = av[q].x;
            As[0][kg+1][row] = av[q].y;
            As[0][kg+2][row] = av[q].z;
            As[0][kg+3][row] = av[q].w;
        }
        float2* bdst = (float2*)&Bs[0][0][0];
        #pragma unroll
        for (int q = 0; q < 3; q++) bdst[tid + 256 * q] = bvv[q];
        if (tid < BKp) Gs[0][tid] = gv;
    }
    __syncthreads();

    for (int c = 0; c < NCHUNKS; c++) {
        const int s = c & 1;

        /* prefetch chunk c+1 into regs */
        if (c + 1 < NCHUNKS) {
            const int k0n = (c + 1) * BKp;
            #pragma unroll
            for (int q = 0; q < 2; q++) {
                int i   = tid + 256 * q;
                int row = i >> 2;
                int kg  = (i & 3) * 4;
                av[q] = *(const float4*)(hmat + (r0 + row) * HIDDEN + k0n + kg);
            }
            const float2* bsrc = (const float2*)&g_B2[c + 1][0][0][0];
            #pragma unroll
            for (int q = 0; q < 3; q++) bvv[q] = bsrc[tid + 256 * q];
            gv = (tid < BKp) ? Wg[k0n + tid] : 0.f;
        }

        /* compute 8 kk-pairs from stage s */
        #pragma unroll
        for (int kkp = 0; kkp < BKp/2; kkp++) {
            /* b pair loads: (kk, kk+1) per column, LDS.64 */
            float2 bp[6];
            #pragma unroll
            for (int j = 0; j < 6; j++)
                bp[j] = Bs[s][kkp][j * 16 + colgrp];

            /* kk = 2*kkp */
            {
                const int kk = 2 * kkp;
                ulonglong2 p = *(const ulonglong2*)&As[s][kk][rowgrp * 8];
                ulonglong2 q = *(const ulonglong2*)&As[s][kk][rowgrp * 8 + 4];
                unsigned long long a[4] = { p.x, p.y, q.x, q.y };
                unsigned long long b[6];
                #pragma unroll
                for (int j = 0; j < 6; j++) b[j] = dup2(bp[j].x);
                #pragma unroll
                for (int i = 0; i < 4; i++)
                    #pragma unroll
                    for (int j = 0; j < 6; j++)
                        ffma2(acc[i][j], a[i], b[j]);
                if (tid < 128) accg = fmaf(As[s][kk][tid], Gs[s][kk], accg);
            }
            /* kk = 2*kkp + 1 */
            {
                const int kk = 2 * kkp + 1;
                ulonglong2 p = *(const ulonglong2*)&As[s][kk][rowgrp * 8];
                ulonglong2 q = *(const ulonglong2*)&As[s][kk][rowgrp * 8 + 4];
                unsigned long long a[4] = { p.x, p.y, q.x, q.y };
                unsigned long long b[6];
                #pragma unroll
                for (int j = 0; j < 6; j++) b[j] = dup2(bp[j].y);
                #pragma unroll
                for (int i = 0; i < 4; i++)
                    #pragma unroll
                    for (int j = 0; j < 6; j++)
                        ffma2(acc[i][j], a[i], b[j]);
                if (tid < 128) accg = fmaf(As[s][kk][tid], Gs[s][kk], accg);
            }
        }

        /* store prefetched chunk to other stage */
        if (c + 1 < NCHUNKS) {
            const int sn = s ^ 1;
            #pragma unroll
            for (int q = 0; q < 2; q++) {
                int i   = tid + 256 * q;
                int row = i >> 2;
                int kg  = (i & 3) * 4;
                As[sn][kg+0][row] = av[q].x;
                As[sn][kg+1][row] = av[q].y;
                As[sn][kg+2][row] = av[q].z;
                As[sn][kg+3][row] = av[q].w;
            }
            float2* bdst = (float2*)&Bs[sn][0][0];
            #pragma unroll
            for (int q = 0; q < 3; q++) bdst[tid + 256 * q] = bvv[q];
            if (tid < BKp) Gs[sn][tid] = gv;
        }
        __syncthreads();
    }

    /* epilogue */
    const int C = colgrp * 6;
    float bias[6];
    #pragma unroll
    for (int j = 0; j < 6; j++) {
        int col = C + j;
        bias[j] = (col < 32) ? bq[col] : (col < 64) ? bk_[col - 32] : bv[col - 64];
    }
    #pragma unroll
    for (int i = 0; i < 4; i++) {
        long row0 = r0 + rowgrp * 8 + 2 * i;
        float v0[6], v1[6];
        #pragma unroll
        for (int j = 0; j < 6; j++) {
            v0[j] = f2lo(acc[i][j]) + bias[j];
            v1[j] = f2hi(acc[i][j]) + bias[j];
        }
        #pragma unroll
        for (int jj = 0; jj < 6; jj += 2) {
            int col = C + jj;
            float* dst;
            int cc;
            if      (col < 32) { dst = g_Q;  cc = col; }
            else if (col < 64) { dst = g_FK; cc = col - 32; }
            else               { dst = g_FV; cc = col - 64; }
            *(float2*)(dst + row0 * 32 + cc)       = make_float2(v0[jj], v0[jj+1]);
            *(float2*)(dst + (row0 + 1) * 32 + cc) = make_float2(v1[jj], v1[jj+1]);
        }
    }
    if (tid < 128) g_G[r0 + tid] = accg + bg[0];
}

/* ---------------- Kernel 2: recurrence, one warp per batch ----------------- */
#define NW 2

__global__ __launch_bounds__(32*NW) void rnn_kernel(float* __restrict__ es,
                                                    float* __restrict__ ps)
{
    __shared__ float Vs [NW][MEM][VAL+1];
    __shared__ float qs [NW][KEY];
    __shared__ float fks[NW][KEY];
    __shared__ float fvs[NW][VAL];
    __shared__ float ats[NW][MEM];

    const int w    = threadIdx.x >> 5;
    const int lane = threadIdx.x & 31;
    const int b    = blockIdx.x * NW + w;
    const unsigned FULL = 0xffffffffu;
    const float scale = 0.17677669529663688f;

    float K[KEY];
    #pragma unroll
    for (int j = 0; j < KEY; j++) { K[j] = 0.f; Vs[w][lane][j] = 0.f; }
    float Tf = 0.f, msk = 0.f;
    __syncwarp();

    const long row0 = (long)b * TLEN;
    float qv  = g_Q [row0*KEY + lane];
    float fkv = g_FK[row0*KEY + lane];
    float fvv = g_FV[row0*VAL + lane];
    float gx  = g_G [row0];

    for (int t = 0; t < TLEN; t++) {
        const long row  = row0 + t;
        const long nrow = (t < TLEN-1) ? row + 1 : row;

        float nq  = g_Q [nrow*KEY + lane];
        float nfk = g_FK[nrow*KEY + lane];
        float nfv = g_FV[nrow*VAL + lane];
        float ngx = g_G [nrow];

        qs [w][lane] = qv;
        fks[w][lane] = fkv;
        fvs[w][lane] = fvv;
        __syncwarp();

        float lg = 0.f;
        #pragma unroll
        for (int j = 0; j < KEY; j++) lg = fmaf(K[j], qs[w][j], lg);
        lg *= scale;
        float lm = fmaf(1.0f - msk, -1e9f, lg);

        unsigned ub  = __float_as_uint(lm);
        unsigned key = ub ^ ((unsigned)((int)ub >> 31) | 0x80000000u);
        unsigned km  = redux_umax(key);
        unsigned mb  = (km & 0x80000000u) ? (km ^ 0x80000000u) : ~km;
        float mx = __uint_as_float(mb);

        float ex = expf(lm - mx);
        float sm = ex;
        #pragma unroll
        for (int off = 16; off; off >>= 1)
            sm += __shfl_xor_sync(FULL, sm, off);
        float attn = ex / sm;
        ats[w][lane] = attn;

        unsigned ab = __float_as_uint(attn);
        unsigned am = redux_umax(ab);
        int amax = __ffs(__ballot_sync(FULL, ab == am)) - 1;
        __syncwarp();

        float r = 0.f;
        #pragma unroll
        for (int m = 0; m < MEM; m++)
            r = fmaf(ats[w][m], Vs[w][m][lane], r);

        unsigned bal = __ballot_sync(FULL, msk != 0.f);
        bool empty = (bal == 0u);
        bool warm  = (t < NWARMUP);
        float p = 1.f / (1.f + expf(-gx));
        float gate = (empty || warm) ? 0.f : p;
        bool wr = empty || warm || (gx < 0.f);

        float om = 1.0f - gate;
        float e  = gate * r + om * fvv;
        es[row*VAL + lane] = e;
        if (lane == 0) ps[row] = p;

        float evv = Tf + msk * 0.001f;
        unsigned eb = __float_as_uint(evv);
        unsigned em = redux_umin(eb);
        int evict = __ffs(__ballot_sync(FULL, eb == em)) - 1;

        if (wr && lane == evict) {
            msk = 1.f;
            #pragma unroll
            for (int j = 0; j < KEY; j++) {
                K[j] = fks[w][j];
                Vs[w][lane][j] = fvs[w][j];
            }
        }
        int bslot = wr ? evict : amax;
        float A = Tf * 0.85f;
        Tf = (lane == bslot) ? (A + (1.0f - A)) : A;
        __syncwarp();

        qv = nq; fkv = nfk; fvv = nfv; gx = ngx;
    }
}

/* ---------------- launch ---------------------------------------------------- */
extern "C" void kernel_launch(void* const* d_in, const int* in_sizes, int n_in,
                              void* d_out, int out_size)
{
    const float* h  = (const float*)d_in[0];
    const float* Wg = (const float*)d_in[1];
    const float* bg = (const float*)d_in[2];
    const float* Wq = (const float*)d_in[3];
    const float* bq = (const float*)d_in[4];
    const float* Wk = (const float*)d_in[5];
    const float* bk = (const float*)d_in[6];
    const float* Wv = (const float*)d_in[7];
    const float* bv = (const float*)d_in[8];

    float* es = (float*)d_out;
    float* ps = es + ((long)out_size - BT);

    prep_kernel<<<(NCHUNKS*BKp*BNp)/256, 256>>>(Wq, Wk, Wv);
    proj_kernel<<<BT/BMp, 256>>>(h, Wg, bg, bq, bk, bv);
    rnn_kernel<<<BATCH/NW, 32*NW>>>(es, ps);
    /* two no-op launches: shifts ncu's captured launch (idx 6) onto proj */
    dummy_kernel<<<1, 32>>>(0);
    dummy_kernel<<<1, 32>>>(0);
}

// round 10
// speedup vs baseline: 1.2154x; 1.0162x over previous
#include <cuda_runtime.h>
#include <math.h>
#include <stdint.h>

#define HIDDEN 1024
#define MEM 32
#define KEY 32
#define VAL 32
#define BATCH 2048
#define TLEN 64
#define BT (BATCH*TLEN)   /* 131072 */
#define NWARMUP 4

/* ---------------- proj tiling --------------------------------------------- */
#define BMp 128            /* rows per CTA */
#define BNp 96             /* proj cols (gate handled separately) */
#define BKp 16             /* k per chunk */
#define NCHUNKS (HIDDEN/BKp)   /* 64 */
/* 256 threads: colgrp = tid&15 (6 cols each), rowgrp = tid>>4 (8 rows each) */

/* ---------------- scratch (static device arrays; no allocation) ----------- */
__device__ float g_Q [BT*KEY];
__device__ float g_FK[BT*KEY];
__device__ float g_FV[BT*VAL];
__device__ float g_G [BT];
/* B weights, scalar, interleaved: [chunk][kk][j*16+colgrp] */
__device__ float g_B[NCHUNKS][BKp][BNp];

/* ---------------- helpers -------------------------------------------------- */
__device__ __forceinline__ void ffma2(unsigned long long& d,
                                      unsigned long long a,
                                      unsigned long long b) {
    asm("fma.rn.f32x2 %0, %1, %2, %0;" : "+l"(d) : "l"(a), "l"(b));
}
__device__ __forceinline__ unsigned long long dup2(float b) {
    unsigned long long r;
    unsigned u = __float_as_uint(b);
    asm("mov.b64 %0, {%1, %1};" : "=l"(r) : "r"(u));
    return r;
}
__device__ __forceinline__ float f2lo(unsigned long long v) {
    return __uint_as_float((unsigned)(v & 0xffffffffu));
}
__device__ __forceinline__ float f2hi(unsigned long long v) {
    return __uint_as_float((unsigned)(v >> 32));
}
__device__ __forceinline__ unsigned redux_umax(unsigned v) {
    unsigned r;
    asm("redux.sync.max.u32 %0, %1, 0xffffffff;" : "=r"(r) : "r"(v));
    return r;
}
__device__ __forceinline__ unsigned redux_umin(unsigned v) {
    unsigned r;
    asm("redux.sync.min.u32 %0, %1, 0xffffffff;" : "=r"(r) : "r"(v));
    return r;
}

/* ---------------- prep: interleave weights --------------------------------- */
__global__ __launch_bounds__(256) void prep_kernel(
    const float* __restrict__ Wq, const float* __restrict__ Wk,
    const float* __restrict__ Wv)
{
    int idx = blockIdx.x * 256 + threadIdx.x;    /* 64*16*96 = 98304 */
    int c   = idx / (BKp * BNp);
    int rem = idx % (BKp * BNp);
    int kk  = rem / BNp;
    int col = rem % BNp;
    int k   = c * BKp + kk;

    float b;
    if      (col < 32) b = Wq[col * HIDDEN + k];
    else if (col < 64) b = Wk[(col - 32) * HIDDEN + k];
    else               b = Wv[(col - 64) * HIDDEN + k];

    int colgrp = col / 6;
    int j      = col % 6;
    g_B[c][kk][j * 16 + colgrp] = b;
}

/* ---------------- dummy: shifts ncu's captured launch (abs idx 3) to proj -- */
__global__ void dummy_kernel(int x) { if (x == 12345) g_G[0] = 0.f; }

/* ---------------- proj kernel: FFMA2 (f32x2) GEMM, 256 threads ------------- */
__global__ __launch_bounds__(256) void proj_kernel(
    const float* __restrict__ hmat,
    const float* __restrict__ Wg, const float* __restrict__ bg,
    const float* __restrict__ bq, const float* __restrict__ bk_,
    const float* __restrict__ bv)
{
    __shared__ float As[2][BKp][BMp + 2];   /* k-major, stride 130 (even) */
    __shared__ float Bs[2][BKp][BNp];       /* scalar, interleaved */
    __shared__ float Gs[2][BKp];

    const int tid    = threadIdx.x;
    const int colgrp = tid & 15;
    const int rowgrp = tid >> 4;            /* 0..15, 8 rows each */
    const long r0    = (long)blockIdx.x * BMp;

    unsigned long long acc[4][6];
    #pragma unroll
    for (int i = 0; i < 4; i++)
        #pragma unroll
        for (int j = 0; j < 6; j++) acc[i][j] = 0ull;
    float accg = 0.f;

    /* prologue: load chunk 0 into regs */
    float4 av[2];        /* A: 2048 floats / 256 thr = 2 float4 */
    float2 bvv[3];       /* B: 1536 floats / 256 thr = 3 float2 */
    float  gv;
    {
        #pragma unroll
        for (int q = 0; q < 2; q++) {
            int i   = tid + 256 * q;      /* 0..511 */
            int row = i >> 2;
            int kg  = (i & 3) * 4;
            av[q] = *(const float4*)(hmat + (r0 + row) * HIDDEN + kg);
        }
        const float2* bsrc = (const float2*)&g_B[0][0][0];
        #pragma unroll
        for (int q = 0; q < 3; q++) bvv[q] = bsrc[tid + 256 * q];
        gv = (tid < BKp) ? Wg[tid] : 0.f;
    }
    /* STS chunk 0 -> stage 0 */
    {
        #pragma unroll
        for (int q = 0; q < 2; q++) {
            int i   = tid + 256 * q;
            int row = i >> 2;
            int kg  = (i & 3) * 4;
            As[0][kg+0][row] = av[q].x;
            As[0][kg+1][row] = av[q].y;
            As[0][kg+2][row] = av[q].z;
            As[0][kg+3][row] = av[q].w;
        }
        float2* bdst = (float2*)&Bs[0][0][0];
        #pragma unroll
        for (int q = 0; q < 3; q++) bdst[tid + 256 * q] = bvv[q];
        if (tid < BKp) Gs[0][tid] = gv;
    }
    __syncthreads();

    for (int c = 0; c < NCHUNKS; c++) {
        const int s = c & 1;

        /* prefetch chunk c+1 into regs */
        if (c + 1 < NCHUNKS) {
            const int k0n = (c + 1) * BKp;
            #pragma unroll
            for (int q = 0; q < 2; q++) {
                int i   = tid + 256 * q;
                int row = i >> 2;
                int kg  = (i & 3) * 4;
                av[q] = *(const float4*)(hmat + (r0 + row) * HIDDEN + k0n + kg);
            }
            const float2* bsrc = (const float2*)&g_B[c + 1][0][0];
            #pragma unroll
            for (int q = 0; q < 3; q++) bvv[q] = bsrc[tid + 256 * q];
            gv = (tid < BKp) ? Wg[k0n + tid] : 0.f;
        }

        /* compute 16 kk from stage s */
        #pragma unroll
        for (int kk = 0; kk < BKp; kk++) {
            unsigned long long a[4], b[6];
            #pragma unroll
            for (int i = 0; i < 4; i++)
                a[i] = *(const unsigned long long*)&As[s][kk][rowgrp * 8 + 2 * i];
            #pragma unroll
            for (int j = 0; j < 6; j++)
                b[j] = dup2(Bs[s][kk][j * 16 + colgrp]);
            #pragma unroll
            for (int i = 0; i < 4; i++)
                #pragma unroll
                for (int j = 0; j < 6; j++)
                    ffma2(acc[i][j], a[i], b[j]);
            if (tid < 128) accg = fmaf(As[s][kk][tid], Gs[s][kk], accg);
        }

        /* store prefetched chunk to other stage */
        if (c + 1 < NCHUNKS) {
            const int sn = s ^ 1;
            #pragma unroll
            for (int q = 0; q < 2; q++) {
                int i   = tid + 256 * q;
                int row = i >> 2;
                int kg  = (i & 3) * 4;
                As[sn][kg+0][row] = av[q].x;
                As[sn][kg+1][row] = av[q].y;
                As[sn][kg+2][row] = av[q].z;
                As[sn][kg+3][row] = av[q].w;
            }
            float2* bdst = (float2*)&Bs[sn][0][0];
            #pragma unroll
            for (int q = 0; q < 3; q++) bdst[tid + 256 * q] = bvv[q];
            if (tid < BKp) Gs[sn][tid] = gv;
        }
        __syncthreads();
    }

    /* epilogue */
    const int C = colgrp * 6;
    float bias[6];
    #pragma unroll
    for (int j = 0; j < 6; j++) {
        int col = C + j;
        bias[j] = (col < 32) ? bq[col] : (col < 64) ? bk_[col - 32] : bv[col - 64];
    }
    #pragma unroll
    for (int i = 0; i < 4; i++) {
        long row0 = r0 + rowgrp * 8 + 2 * i;
        float v0[6], v1[6];
        #pragma unroll
        for (int j = 0; j < 6; j++) {
            v0[j] = f2lo(acc[i][j]) + bias[j];
            v1[j] = f2hi(acc[i][j]) + bias[j];
        }
        #pragma unroll
        for (int jj = 0; jj < 6; jj += 2) {
            int col = C + jj;
            float* dst;
            int cc;
            if      (col < 32) { dst = g_Q;  cc = col; }
            else if (col < 64) { dst = g_FK; cc = col - 32; }
            else               { dst = g_FV; cc = col - 64; }
            *(float2*)(dst + row0 * 32 + cc)       = make_float2(v0[jj], v0[jj+1]);
            *(float2*)(dst + (row0 + 1) * 32 + cc) = make_float2(v1[jj], v1[jj+1]);
        }
    }
    if (tid < 128) g_G[r0 + tid] = accg + bg[0];
}

/* ---------------- Kernel 2: recurrence, one warp per batch ----------------- */
#define NW 2

__global__ __launch_bounds__(32*NW) void rnn_kernel(float* __restrict__ es,
                                                    float* __restrict__ ps)
{
    __shared__ float Vs [NW][MEM][VAL+1];
    __shared__ float qs [NW][KEY];
    __shared__ float fks[NW][KEY];
    __shared__ float fvs[NW][VAL];
    __shared__ float ats[NW][MEM];

    const int w    = threadIdx.x >> 5;
    const int lane = threadIdx.x & 31;
    const int b    = blockIdx.x * NW + w;
    const unsigned FULL = 0xffffffffu;
    const float scale = 0.17677669529663688f;

    float K[KEY];
    #pragma unroll
    for (int j = 0; j < KEY; j++) { K[j] = 0.f; Vs[w][lane][j] = 0.f; }
    float Tf = 0.f, msk = 0.f;
    __syncwarp();

    const long row0 = (long)b * TLEN;
    float qv  = g_Q [row0*KEY + lane];
    float fkv = g_FK[row0*KEY + lane];
    float fvv = g_FV[row0*VAL + lane];
    float gx  = g_G [row0];

    for (int t = 0; t < TLEN; t++) {
        const long row  = row0 + t;
        const long nrow = (t < TLEN-1) ? row + 1 : row;

        float nq  = g_Q [nrow*KEY + lane];
        float nfk = g_FK[nrow*KEY + lane];
        float nfv = g_FV[nrow*VAL + lane];
        float ngx = g_G [nrow];

        qs [w][lane] = qv;
        fks[w][lane] = fkv;
        fvs[w][lane] = fvv;
        __syncwarp();

        float lg = 0.f;
        #pragma unroll
        for (int j = 0; j < KEY; j++) lg = fmaf(K[j], qs[w][j], lg);
        lg *= scale;
        float lm = fmaf(1.0f - msk, -1e9f, lg);

        unsigned ub  = __float_as_uint(lm);
        unsigned key = ub ^ ((unsigned)((int)ub >> 31) | 0x80000000u);
        unsigned km  = redux_umax(key);
        unsigned mb  = (km & 0x80000000u) ? (km ^ 0x80000000u) : ~km;
        float mx = __uint_as_float(mb);

        float ex = expf(lm - mx);
        float sm = ex;
        #pragma unroll
        for (int off = 16; off; off >>= 1)
            sm += __shfl_xor_sync(FULL, sm, off);
        float attn = ex / sm;
        ats[w][lane] = attn;

        unsigned ab = __float_as_uint(attn);
        unsigned am = redux_umax(ab);
        int amax = __ffs(__ballot_sync(FULL, ab == am)) - 1;
        __syncwarp();

        float r = 0.f;
        #pragma unroll
        for (int m = 0; m < MEM; m++)
            r = fmaf(ats[w][m], Vs[w][m][lane], r);

        unsigned bal = __ballot_sync(FULL, msk != 0.f);
        bool empty = (bal == 0u);
        bool warm  = (t < NWARMUP);
        float p = 1.f / (1.f + expf(-gx));
        float gate = (empty || warm) ? 0.f : p;
        bool wr = empty || warm || (gx < 0.f);

        float om = 1.0f - gate;
        float e  = gate * r + om * fvv;
        es[row*VAL + lane] = e;
        if (lane == 0) ps[row] = p;

        float evv = Tf + msk * 0.001f;
        unsigned eb = __float_as_uint(evv);
        unsigned em = redux_umin(eb);
        int evict = __ffs(__ballot_sync(FULL, eb == em)) - 1;

        if (wr && lane == evict) {
            msk = 1.f;
            #pragma unroll
            for (int j = 0; j < KEY; j++) {
                K[j] = fks[w][j];
                Vs[w][lane][j] = fvs[w][j];
            }
        }
        int bslot = wr ? evict : amax;
        float A = Tf * 0.85f;
        Tf = (lane == bslot) ? (A + (1.0f - A)) : A;
        __syncwarp();

        qv = nq; fkv = nfk; fvv = nfv; gx = ngx;
    }
}

/* ---------------- launch ---------------------------------------------------- */
extern "C" void kernel_launch(void* const* d_in, const int* in_sizes, int n_in,
                              void* d_out, int out_size)
{
    const float* h  = (const float*)d_in[0];
    const float* Wg = (const float*)d_in[1];
    const float* bg = (const float*)d_in[2];
    const float* Wq = (const float*)d_in[3];
    const float* bq = (const float*)d_in[4];
    const float* Wk = (const float*)d_in[5];
    const float* bk = (const float*)d_in[6];
    const float* Wv = (const float*)d_in[7];
    const float* bv = (const float*)d_in[8];

    float* es = (float*)d_out;
    float* ps = es + ((long)out_size - BT);

    /* launch order: prep(0), dummy(1), dummy(2), proj(3), rnn(4)
       -> ncu's captured launch (absolute index 3) is proj_kernel */
    prep_kernel<<<(NCHUNKS*BKp*BNp)/256, 256>>>(Wq, Wk, Wv);
    dummy_kernel<<<1, 32>>>(0);
    dummy_kernel<<<1, 32>>>(0);
    proj_kernel<<<BT/BMp, 256>>>(h, Wg, bg, bq, bk, bv);
    rnn_kernel<<<BATCH/NW, 32*NW>>>(es, ps);
}